// round 6
// baseline (speedup 1.0000x reference)
#include <cuda_runtime.h>
#include <cuda_bf16.h>
#include <cstdint>

// EngramMemory: rolling-hash n-gram gather — inverted "slice-scan" formulation.
//
// tokens: (4, 4096) int32, tables: (8, 2048, 256) f32, out: (4, 4096, 2048) f32
// out[bs][part*256 + d] = tables[part][h(part,bs)][d]
//   h = fold over order-(2+oi) n-gram: h = (h*1000003 + tok + seed) & 2047,
//   seed = 1337 + 97*(2+oi) + 17*head, left zero-padded. All math fits in u32.
//
// R5: instead of gathering 128 MiB from L2 (each table row read 8x on average),
// each CTA owns one (part, 128-bucket slice) = 128 KB of table, bulk-loads it
// into SMEM once, recomputes all 16384 hashes for its part, and copies the
// ~1024 matching rows SMEM -> GMEM. L2 traffic drops 268 MB -> ~160 MB.

namespace {
constexpr int S = 4096;
constexpr int BS = 16384;               // B * S
constexpr int NUM_BUCKETS = 2048;
constexpr int HEAD_DIM = 256;
constexpr int SLICES = 16;              // bucket ranges per part
constexpr int SLICE_BUCKETS = NUM_BUCKETS / SLICES;   // 128
constexpr int SLICE_BYTES = SLICE_BUCKETS * HEAD_DIM * 4;  // 128 KB
constexpr int THREADS = 512;
constexpr int LIST_CAP = 1536;          // matches ~ Binom(16384, 1/16): mean 1024, sd 31
constexpr unsigned PRIME = 1000003u;

// Dynamic smem layout:
//   [0, 8)        mbarrier
//   [8, 12)       match count
//   [16, 16+4*LIST_CAP)  match list (packed: p<<7 | local_h)
//   [8192, 8192+SLICE_BYTES)  table slice rows (1 KB per bucket)
constexpr int SM_MBAR = 0;
constexpr int SM_CNT  = 8;
constexpr int SM_LIST = 16;
constexpr int SM_ROWS = 8192;
constexpr int SMEM_TOTAL = SM_ROWS + SLICE_BYTES;   // 139264 B

__device__ __forceinline__ uint32_t smem_u32(const void* p) {
    uint32_t a;
    asm("{ .reg .u64 t; cvta.to.shared.u64 t, %1; cvt.u32.u64 %0, t; }"
        : "=r"(a) : "l"(p));
    return a;
}

__global__ __launch_bounds__(THREADS, 1)
void engram_slice_kernel(const int*   __restrict__ tokens,
                         const float* __restrict__ tables,
                         float*       __restrict__ out) {
    extern __shared__ char smem[];
    const uint32_t smem_base = smem_u32(smem);
    const int tid = threadIdx.x;

    const int part  = blockIdx.x >> 4;      // 0..7
    const int slice = blockIdx.x & (SLICES - 1);
    const unsigned base = slice * SLICE_BUCKETS;

    unsigned* cnt   = reinterpret_cast<unsigned*>(smem + SM_CNT);
    unsigned* list  = reinterpret_cast<unsigned*>(smem + SM_LIST);
    const uint32_t mbar = smem_base + SM_MBAR;

    // ---- Fill: bulk-load this CTA's 128 KB table slice into SMEM ----------
    if (tid == 0) {
        *cnt = 0;
        asm volatile("mbarrier.init.shared.b64 [%0], 1;" :: "r"(mbar) : "memory");
        asm volatile("mbarrier.arrive.expect_tx.shared.b64 _, [%0], %1;"
                     :: "r"(mbar), "r"((unsigned)SLICE_BYTES) : "memory");
        const char* gsrc = reinterpret_cast<const char*>(
            tables + ((size_t)part * NUM_BUCKETS + base) * HEAD_DIM);
        #pragma unroll
        for (int i = 0; i < 8; i++) {
            asm volatile(
                "cp.async.bulk.shared::cta.global.mbarrier::complete_tx::bytes "
                "[%0], [%1], %2, [%3];"
                :: "r"(smem_base + SM_ROWS + i * (SLICE_BYTES / 8)),
                   "l"(gsrc + i * (SLICE_BYTES / 8)),
                   "r"((unsigned)(SLICE_BYTES / 8)),
                   "r"(mbar)
                : "memory");
        }
    }
    __syncthreads();   // cnt=0 and mbarrier.init visible to all

    // ---- Scan: recompute all 16384 hashes for this part, collect matches --
    const int oi    = part >> 2;
    const int head  = part & 3;
    const int order = 2 + oi;
    const unsigned seed = 1337u + 97u * (unsigned)order + 17u * (unsigned)head;

    for (int p = tid; p < BS; p += THREADS) {
        const int b = p >> 12;
        const int s = p & (S - 1);
        unsigned h = 0u;
        #pragma unroll 3
        for (int i = 0; i < order; i++) {
            const int pos = s - order + 1 + i;
            unsigned tok = 0u;
            if (pos >= 0) tok = (unsigned)__ldg(tokens + b * S + pos);
            h = (h * PRIME + tok + seed) & (NUM_BUCKETS - 1);
        }
        const unsigned lh = h - base;
        if (lh < (unsigned)SLICE_BUCKETS) {
            const unsigned idx = atomicAdd(cnt, 1u);
            if (idx < LIST_CAP) list[idx] = ((unsigned)p << 7) | lh;
        }
    }
    __syncthreads();   // list complete

    // ---- Wait for the slice fill ------------------------------------------
    {
        uint32_t done;
        asm volatile(
            "{\n\t.reg .pred p;\n\t"
            "mbarrier.try_wait.parity.acquire.cta.shared::cta.b64 p, [%1], 0;\n\t"
            "selp.b32 %0, 1, 0, p;\n\t}"
            : "=r"(done) : "r"(mbar) : "memory");
        while (!done) {
            asm volatile(
                "{\n\t.reg .pred p;\n\t"
                "mbarrier.try_wait.parity.acquire.cta.shared::cta.b64 p, [%1], 0, 0x989680;\n\t"
                "selp.b32 %0, 1, 0, p;\n\t}"
                : "=r"(done) : "r"(mbar) : "memory");
        }
    }

    // ---- Copy: each warp streams one matched 1 KB row per iteration -------
    const int n    = min(*cnt, (unsigned)LIST_CAP);
    const int lane = tid & 31;
    const int w    = tid >> 5;

    const float4* rows = reinterpret_cast<const float4*>(smem + SM_ROWS);
    for (int m = w; m < n; m += THREADS / 32) {
        const unsigned e  = list[m];
        const int      p  = e >> 7;
        const unsigned lh = e & (SLICE_BUCKETS - 1);
        const float4* src = rows + lh * (HEAD_DIM / 4) + lane;
        float4* dst = reinterpret_cast<float4*>(
            out + (size_t)p * (8 * HEAD_DIM) + part * HEAD_DIM) + lane;
        dst[0]  = src[0];
        dst[32] = src[32];
    }
}
} // namespace

extern "C" void kernel_launch(void* const* d_in, const int* in_sizes, int n_in,
                              void* d_out, int out_size) {
    // Resolve input order by element count: tokens = 16384, tables = 4194304.
    int ti = 0, wi = 1;
    if (n_in >= 2 && in_sizes[0] > in_sizes[1]) { ti = 1; wi = 0; }
    const int*   tokens = (const int*)d_in[ti];
    const float* tables = (const float*)d_in[wi];
    float*       out    = (float*)d_out;

    static bool attr_done = false;
    cudaFuncSetAttribute(engram_slice_kernel,
                         cudaFuncAttributeMaxDynamicSharedMemorySize, SMEM_TOTAL);
    (void)attr_done;

    engram_slice_kernel<<<8 * SLICES, THREADS, SMEM_TOTAL>>>(tokens, tables, out);
}

// round 7
// speedup vs baseline: 1.0554x; 1.0554x over previous
#include <cuda_runtime.h>
#include <cuda_bf16.h>
#include <cstdint>

// EngramMemory: rolling-hash n-gram gather — slice-scan v2.
//
// tokens: (4, 4096) int32, tables: (8, 2048, 256) f32, out: (4, 4096, 2048) f32
// out[p][part*256 + d] = tables[part][h(part,p)][d]
//   h = fold over order-(2+oi) n-gram: h = (h*1000003 + tok + seed) & 2047,
//   seed = 1337 + 97*(2+oi) + 17*head, left zero-padded. All math fits in u32.
//
// R6: 256 CTAs, each owning one (part, 64-bucket slice) = 64 KB of table.
//  - TMA bulk fill of the slice, overlapped with the hash scan.
//  - Per-warp ballot-compacted match lists (no shared atomics).
//  - Each warp copies its own matches SMEM->GMEM (no CTA-wide barrier between
//    scan and copy; only the TMA mbarrier gates the copy).
// L2 traffic ~155 MB (writes + fills + tokens) vs 268 MB for the direct gather.

namespace {
constexpr int S = 4096;
constexpr int BS = 16384;               // B * S
constexpr int NUM_BUCKETS = 2048;
constexpr int HEAD_DIM = 256;
constexpr int SLICES = 32;              // bucket ranges per part
constexpr int SLICE_BUCKETS = NUM_BUCKETS / SLICES;        // 64
constexpr int SLICE_BYTES = SLICE_BUCKETS * HEAD_DIM * 4;  // 64 KB
constexpr int THREADS = 512;
constexpr int WARPS = THREADS / 32;     // 16
constexpr int POS_PER_WARP = BS / WARPS;  // 1024
constexpr int CAP_W = 96;               // per-warp list cap (mean 32, sd 5.6)
constexpr unsigned PRIME = 1000003u;

// Dynamic smem layout:
//   [0, 8)                    mbarrier
//   [16, 16 + 4*16*CAP_W)     per-warp match lists
//   [8192, 8192+SLICE_BYTES)  table slice rows (1 KB per bucket)
constexpr int SM_MBAR = 0;
constexpr int SM_LIST = 16;
constexpr int SM_ROWS = 8192;
constexpr int SMEM_TOTAL = SM_ROWS + SLICE_BYTES;   // 73728 B -> 2 CTAs/SM

__device__ __forceinline__ uint32_t smem_u32(const void* p) {
    uint32_t a;
    asm("{ .reg .u64 t; cvta.to.shared.u64 t, %1; cvt.u32.u64 %0, t; }"
        : "=r"(a) : "l"(p));
    return a;
}

__global__ __launch_bounds__(THREADS, 2)
void engram_slice_kernel(const int*   __restrict__ tokens,
                         const float* __restrict__ tables,
                         float*       __restrict__ out) {
    extern __shared__ char smem[];
    const uint32_t smem_base = smem_u32(smem);
    const int tid  = threadIdx.x;
    const int w    = tid >> 5;
    const int lane = tid & 31;

    const int part  = blockIdx.x >> 5;          // 0..7
    const int slice = blockIdx.x & (SLICES - 1);
    const unsigned base = slice * SLICE_BUCKETS;

    const uint32_t mbar = smem_base + SM_MBAR;

    // ---- Fill: TMA bulk-load this CTA's 64 KB table slice into SMEM -------
    if (tid == 0) {
        asm volatile("mbarrier.init.shared.b64 [%0], 1;" :: "r"(mbar) : "memory");
        asm volatile("mbarrier.arrive.expect_tx.shared.b64 _, [%0], %1;"
                     :: "r"(mbar), "r"((unsigned)SLICE_BYTES) : "memory");
        const char* gsrc = reinterpret_cast<const char*>(
            tables + ((size_t)part * NUM_BUCKETS + base) * HEAD_DIM);
        #pragma unroll
        for (int i = 0; i < 8; i++) {
            asm volatile(
                "cp.async.bulk.shared::cta.global.mbarrier::complete_tx::bytes "
                "[%0], [%1], %2, [%3];"
                :: "r"(smem_base + SM_ROWS + i * (SLICE_BYTES / 8)),
                   "l"(gsrc + i * (SLICE_BYTES / 8)),
                   "r"((unsigned)(SLICE_BYTES / 8)),
                   "r"(mbar)
                : "memory");
        }
    }
    __syncthreads();   // mbarrier.init visible to all warps before their wait

    // ---- Scan: this warp's 1024 positions; ballot-compact matches ---------
    const int oi    = part >> 2;
    const int head  = part & 3;
    const int order = 2 + oi;
    const unsigned seed = 1337u + 97u * (unsigned)order + 17u * (unsigned)head;

    unsigned* wlist = reinterpret_cast<unsigned*>(smem + SM_LIST) + w * CAP_W;
    const unsigned lmask_lt = (1u << lane) - 1u;
    int cnt = 0;

    const int p0 = w * POS_PER_WARP + lane;
    #pragma unroll 4
    for (int it = 0; it < POS_PER_WARP / 32; it++) {
        const int p = p0 + it * 32;
        const int b = p >> 12;
        const int s = p & (S - 1);
        unsigned h = 0u;
        #pragma unroll 3
        for (int i = 0; i < order; i++) {
            const int pos = s - order + 1 + i;
            unsigned tok = 0u;
            if (pos >= 0) tok = (unsigned)__ldg(tokens + b * S + pos);
            h = (h * PRIME + tok + seed) & (NUM_BUCKETS - 1);
        }
        const unsigned lh = h - base;
        const bool m = lh < (unsigned)SLICE_BUCKETS;
        const unsigned bal = __ballot_sync(0xffffffffu, m);
        if (m) {
            const int idx = cnt + __popc(bal & lmask_lt);
            if (idx < CAP_W) wlist[idx] = ((unsigned)p << 6) | lh;
        }
        cnt += __popc(bal);
    }
    if (cnt > CAP_W) cnt = CAP_W;

    // ---- Wait for the slice fill (per-thread poll; no CTA barrier) --------
    {
        uint32_t done;
        asm volatile(
            "{\n\t.reg .pred p;\n\t"
            "mbarrier.try_wait.parity.acquire.cta.shared::cta.b64 p, [%1], 0;\n\t"
            "selp.b32 %0, 1, 0, p;\n\t}"
            : "=r"(done) : "r"(mbar) : "memory");
        while (!done) {
            asm volatile(
                "{\n\t.reg .pred p;\n\t"
                "mbarrier.try_wait.parity.acquire.cta.shared::cta.b64 p, [%1], 0, 0x989680;\n\t"
                "selp.b32 %0, 1, 0, p;\n\t}"
                : "=r"(done) : "r"(mbar) : "memory");
        }
    }

    // ---- Copy: this warp streams its own matched 1 KB rows ----------------
    const float4* rows = reinterpret_cast<const float4*>(smem + SM_ROWS);
    float4* outv = reinterpret_cast<float4*>(out);
    const int dbase = part * (HEAD_DIM / 4) + lane;

    int m = 0;
    for (; m + 2 <= cnt; m += 2) {
        const unsigned e0 = wlist[m];
        const unsigned e1 = wlist[m + 1];
        const float4* s0 = rows + (e0 & 63u) * (HEAD_DIM / 4) + lane;
        const float4* s1 = rows + (e1 & 63u) * (HEAD_DIM / 4) + lane;
        float4 a0 = s0[0], b0 = s0[32];
        float4 a1 = s1[0], b1 = s1[32];
        float4* d0 = outv + (size_t)(e0 >> 6) * 512 + dbase;
        float4* d1 = outv + (size_t)(e1 >> 6) * 512 + dbase;
        d0[0] = a0; d0[32] = b0;
        d1[0] = a1; d1[32] = b1;
    }
    if (m < cnt) {
        const unsigned e0 = wlist[m];
        const float4* s0 = rows + (e0 & 63u) * (HEAD_DIM / 4) + lane;
        float4 a0 = s0[0], b0 = s0[32];
        float4* d0 = outv + (size_t)(e0 >> 6) * 512 + dbase;
        d0[0] = a0; d0[32] = b0;
    }
}
} // namespace

extern "C" void kernel_launch(void* const* d_in, const int* in_sizes, int n_in,
                              void* d_out, int out_size) {
    // Resolve input order by element count: tokens = 16384, tables = 4194304.
    int ti = 0, wi = 1;
    if (n_in >= 2 && in_sizes[0] > in_sizes[1]) { ti = 1; wi = 0; }
    const int*   tokens = (const int*)d_in[ti];
    const float* tables = (const float*)d_in[wi];
    float*       out    = (float*)d_out;

    cudaFuncSetAttribute(engram_slice_kernel,
                         cudaFuncAttributeMaxDynamicSharedMemorySize, SMEM_TOTAL);
    engram_slice_kernel<<<8 * SLICES, THREADS, SMEM_TOTAL>>>(tokens, tables, out);
}

// round 10
// speedup vs baseline: 1.5208x; 1.4409x over previous
#include <cuda_runtime.h>
#include <cuda_bf16.h>
#include <cstdint>

// EngramMemory: rolling-hash n-gram gather — direct gather, tuned (R8/R9).
//
// tokens: (4, 4096) int32, tables: (8, 2048, 256) f32, out: (4, 4096, 2048) f32
// out[p][part*256 + d] = tables[part][h(part,p)][d]
//   h = fold over order-(2+oi) n-gram: h = (h*1000003 + tok + seed) & 2047,
//   seed = 1337 + 97*(2+oi) + 17*head, left zero-padded. All math fits in u32.
//
// R9 = R8 resubmitted verbatim (previous round was a broker/container failure,
// the kernel never executed).
//  - 16 rows per CTA (two 8-deep load/store batches), grid 1024.
//  - Table reads hinted evict_last via createpolicy + L2::cache_hint ->
//    16 MB table pinned in L2; output writes __stcs (evict-first) so the
//    134 MB write stream can't displace it.

namespace {
constexpr int B = 4;
constexpr int S = 4096;
constexpr int NUM_BUCKETS = 2048;
constexpr int HEAD_DIM = 256;
constexpr int PARTS = 8;                        // 2 orders * 4 heads
constexpr int OUT_ROW4 = PARTS * HEAD_DIM / 4;  // 512 float4 per (b,s) row
constexpr int ROWS = 16;                        // output rows per CTA
constexpr int BATCH = 8;                        // rows per load/store burst
constexpr unsigned PRIME = 1000003u;

__device__ __forceinline__ float4 ldg_evict_last(const float4* p, uint64_t pol) {
    float4 v;
    asm volatile("ld.global.nc.L2::cache_hint.v4.f32 {%0,%1,%2,%3}, [%4], %5;"
                 : "=f"(v.x), "=f"(v.y), "=f"(v.z), "=f"(v.w)
                 : "l"(p), "l"(pol));
    return v;
}

__global__ __launch_bounds__(512, 2)
void engram_kernel(const int*   __restrict__ tokens,
                   const float* __restrict__ tables,
                   float*       __restrict__ out) {
    const int row0 = blockIdx.x * ROWS;     // base bs index
    const int tid  = threadIdx.x;

    __shared__ unsigned hidx[ROWS][PARTS];

    // ---- Hashes for all 16 rows (128 threads) -----------------------------
    if (tid < ROWS * PARTS) {
        const int r    = tid >> 3;
        const int part = tid & 7;
        const int bs   = row0 + r;
        const int b    = bs >> 12;          // / 4096
        const int s    = bs & (S - 1);      // % 4096
        const int oi    = part >> 2;        // 0 or 1
        const int head  = part & 3;
        const int order = 2 + oi;
        const unsigned seed = 1337u + 97u * (unsigned)order + 17u * (unsigned)head;
        unsigned h = 0u;
        #pragma unroll 3
        for (int i = 0; i < order; i++) {
            const int pos = s - order + 1 + i;
            unsigned tok = 0u;
            if (pos >= 0) tok = (unsigned)tokens[b * S + pos];
            h = (h * PRIME + tok + seed) & (NUM_BUCKETS - 1);
        }
        hidx[r][part] = h;
    }
    __syncthreads();

    // L2 access policy: evict_last for the table reads.
    uint64_t pol;
    asm("createpolicy.fractional.L2::evict_last.b64 %0, 1.0;" : "=l"(pol));

    // ---- Gather/scatter: each thread moves one float4 per row -------------
    const int c    = tid;                   // float4 index within a row
    const int part = c >> 6;                // 64 float4 per 256-float head slice
    const int d4   = c & 63;

    const float4* __restrict__ tbl =
        reinterpret_cast<const float4*>(tables) +
        (size_t)part * (NUM_BUCKETS * HEAD_DIM / 4) + d4;
    float4* __restrict__ dst =
        reinterpret_cast<float4*>(out) + (size_t)row0 * OUT_ROW4 + c;

    #pragma unroll
    for (int batch = 0; batch < ROWS / BATCH; batch++) {
        const int rb = batch * BATCH;
        float4 v[BATCH];
        #pragma unroll
        for (int j = 0; j < BATCH; j++) {
            v[j] = ldg_evict_last(tbl + (size_t)hidx[rb + j][part] * (HEAD_DIM / 4), pol);
        }
        #pragma unroll
        for (int j = 0; j < BATCH; j++) {
            __stcs(dst + (rb + j) * OUT_ROW4, v[j]);
        }
    }
}
} // namespace

extern "C" void kernel_launch(void* const* d_in, const int* in_sizes, int n_in,
                              void* d_out, int out_size) {
    // Resolve input order by element count: tokens = 16384, tables = 4194304.
    int ti = 0, wi = 1;
    if (n_in >= 2 && in_sizes[0] > in_sizes[1]) { ti = 1; wi = 0; }
    const int*   tokens = (const int*)d_in[ti];
    const float* tables = (const float*)d_in[wi];
    float*       out    = (float*)d_out;

    engram_kernel<<<(B * S) / ROWS, 512>>>(tokens, tables, out);
}

// round 11
// speedup vs baseline: 1.6192x; 1.0647x over previous
#include <cuda_runtime.h>
#include <cuda_bf16.h>
#include <cstdint>

// EngramMemory: rolling-hash n-gram gather — direct gather, tuned (R10).
//
// tokens: (4, 4096) int32, tables: (8, 2048, 256) f32, out: (4, 4096, 2048) f32
// out[p][part*256 + d] = tables[part][h(part,p)][d]
//   h = fold over order-(2+oi) n-gram: h = (h*1000003 + tok + seed) & 2047,
//   seed = 1337 + 97*(2+oi) + 17*head, left zero-padded. All math fits in u32.
//
// R10: revert ROWS to 8 (R9's ROWS=16 pushed regs 40->62 and occupancy
// 62%->43% -- the regression). __launch_bounds__(512,3) pins regs <= 42 so
// 3 CTAs/SM are resident. Keep evict_last table loads + __stcs stores.

namespace {
constexpr int B = 4;
constexpr int S = 4096;
constexpr int NUM_BUCKETS = 2048;
constexpr int HEAD_DIM = 256;
constexpr int PARTS = 8;                        // 2 orders * 4 heads
constexpr int OUT_ROW4 = PARTS * HEAD_DIM / 4;  // 512 float4 per (b,s) row
constexpr int ROWS = 8;                         // output rows per CTA
constexpr unsigned PRIME = 1000003u;

__device__ __forceinline__ float4 ldg_evict_last(const float4* p, uint64_t pol) {
    float4 v;
    asm volatile("ld.global.nc.L2::cache_hint.v4.f32 {%0,%1,%2,%3}, [%4], %5;"
                 : "=f"(v.x), "=f"(v.y), "=f"(v.z), "=f"(v.w)
                 : "l"(p), "l"(pol));
    return v;
}

__global__ __launch_bounds__(512, 3)
void engram_kernel(const int*   __restrict__ tokens,
                   const float* __restrict__ tables,
                   float*       __restrict__ out) {
    const int row0 = blockIdx.x * ROWS;     // base bs index
    const int tid  = threadIdx.x;

    __shared__ unsigned hidx[ROWS][PARTS];

    // ---- Hashes for all 8 rows (64 threads) -------------------------------
    if (tid < ROWS * PARTS) {
        const int r    = tid >> 3;
        const int part = tid & 7;
        const int bs   = row0 + r;
        const int b    = bs >> 12;          // / 4096
        const int s    = bs & (S - 1);      // % 4096
        const int oi    = part >> 2;        // 0 or 1
        const int head  = part & 3;
        const int order = 2 + oi;
        const unsigned seed = 1337u + 97u * (unsigned)order + 17u * (unsigned)head;
        unsigned h = 0u;
        #pragma unroll 3
        for (int i = 0; i < order; i++) {
            const int pos = s - order + 1 + i;
            unsigned tok = 0u;
            if (pos >= 0) tok = (unsigned)tokens[b * S + pos];
            h = (h * PRIME + tok + seed) & (NUM_BUCKETS - 1);
        }
        hidx[r][part] = h;
    }
    __syncthreads();

    // L2 access policy: evict_last for the table reads.
    uint64_t pol;
    asm("createpolicy.fractional.L2::evict_last.b64 %0, 1.0;" : "=l"(pol));

    // ---- Gather/scatter: each thread moves one float4 per row -------------
    const int c    = tid;                   // float4 index within a row
    const int part = c >> 6;                // 64 float4 per 256-float head slice
    const int d4   = c & 63;

    const float4* __restrict__ tbl =
        reinterpret_cast<const float4*>(tables) +
        (size_t)part * (NUM_BUCKETS * HEAD_DIM / 4) + d4;
    float4* __restrict__ dst =
        reinterpret_cast<float4*>(out) + (size_t)row0 * OUT_ROW4 + c;

    float4 v[ROWS];
    #pragma unroll
    for (int j = 0; j < ROWS; j++) {
        v[j] = ldg_evict_last(tbl + (size_t)hidx[j][part] * (HEAD_DIM / 4), pol);
    }
    #pragma unroll
    for (int j = 0; j < ROWS; j++) {
        __stcs(dst + j * OUT_ROW4, v[j]);
    }
}
} // namespace

extern "C" void kernel_launch(void* const* d_in, const int* in_sizes, int n_in,
                              void* d_out, int out_size) {
    // Resolve input order by element count: tokens = 16384, tables = 4194304.
    int ti = 0, wi = 1;
    if (n_in >= 2 && in_sizes[0] > in_sizes[1]) { ti = 1; wi = 0; }
    const int*   tokens = (const int*)d_in[ti];
    const float* tables = (const float*)d_in[wi];
    float*       out    = (float*)d_out;

    engram_kernel<<<(B * S) / ROWS, 512>>>(tokens, tables, out);
}